// round 12
// baseline (speedup 1.0000x reference)
#include <cuda_runtime.h>
#include <math.h>

#define Bd 2
#define Nd 512
#define CSd 256
#define CZd 128
#define Cd 128
#define Hd 8
#define PQKd 8
#define PVd 12
#define HCd (Hd*Cd)          // 1024
#define NPROJ 3744           // 1024 q + 2048 kv + 192 qp + 480 kvp
#define FEAT 2432            // 1024 o + 288 opt + 96 norm + 1024 opair

#define QK_SCALE 0.05103103630798287f   // sqrt(1/384)
#define BIAS_COEF 0.5773502691896258f   // sqrt(1/3)
#define PT_COEF 0.09622504486493763f    // sqrt(1/108)

// ---------------- scratch (device globals; no allocation allowed) ------------
__device__ float g_q[Bd*Nd*HCd];
__device__ float g_k[Bd*Nd*HCd];
__device__ float g_v[Bd*Nd*HCd];
__device__ float g_qpts[Bd*Nd*Hd*PQKd*3];
__device__ float g_kpts[Bd*Nd*Hd*PQKd*3];
__device__ float g_vpts[Bd*Nd*Hd*PVd*3];
__device__ float g_a[Bd*Hd*Nd*Nd];
__device__ float g_feats[Bd*Nd*FEAT];

// ---------------- kernel 1: projections + RoPE + rigid transform -------------
#define TJ1 8
__global__ void k_proj(const float* __restrict__ s,
                       const float* __restrict__ rot,
                       const float* __restrict__ trans,
                       const float* __restrict__ wq,  const float* __restrict__ bq,
                       const float* __restrict__ wkv, const float* __restrict__ bkv,
                       const float* __restrict__ wqp, const float* __restrict__ bqp,
                       const float* __restrict__ wkvp,const float* __restrict__ bkvp)
{
    extern __shared__ float sh[];
    float* s_s = sh;                    // TJ1*256
    float* raw = sh + TJ1*CSd;          // TJ1*NPROJ
    const int tid  = threadIdx.x;
    const int tok0 = blockIdx.x * TJ1;

    for (int idx = tid; idx < TJ1*CSd/4; idx += 256)
        ((float4*)s_s)[idx] = ((const float4*)(s + (size_t)tok0*CSd))[idx];
    __syncthreads();

    for (int oi = tid; oi < NPROJ; oi += 256) {
        const float* wrow; float bias;
        if (oi < 1024)      { wrow = wq   + oi*CSd;        bias = bq[oi]; }
        else if (oi < 3072) { wrow = wkv  + (oi-1024)*CSd; bias = bkv[oi-1024]; }
        else if (oi < 3264) { wrow = wqp  + (oi-3072)*CSd; bias = bqp[oi-3072]; }
        else                { wrow = wkvp + (oi-3264)*CSd; bias = bkvp[oi-3264]; }
        float acc[TJ1];
        #pragma unroll
        for (int t = 0; t < TJ1; t++) acc[t] = 0.0f;
        const float4* w4 = (const float4*)wrow;
        for (int k4 = 0; k4 < CSd/4; k4++) {
            float4 w = w4[k4];
            #pragma unroll
            for (int t = 0; t < TJ1; t++) {
                const float* sp = s_s + t*CSd + k4*4;
                acc[t] = fmaf(w.x, sp[0], acc[t]);
                acc[t] = fmaf(w.y, sp[1], acc[t]);
                acc[t] = fmaf(w.z, sp[2], acc[t]);
                acc[t] = fmaf(w.w, sp[3], acc[t]);
            }
        }
        #pragma unroll
        for (int t = 0; t < TJ1; t++) raw[t*NPROJ + oi] = acc[t] + bias;
    }
    __syncthreads();

    for (int t = 0; t < TJ1; t++) {
        const int tok = tok0 + t;
        const int n   = tok % Nd;
        const float* R = rot + tok*9;
        const float* T = trans + tok*3;
        const float* rw = raw + t*NPROJ;
        for (int job = tid; job < 3296; job += 256) {
            if (job < 2048) {
                // RoPE for q (job<1024) and k
                const int e = job & 1023;
                const int h = e >> 7, c = e & 127;
                const int d = c & 63;
                float ang = (float)n * expf(-(float)(2*d) * (9.210340371976184f/128.0f));
                // FIX (round 11): sincosf writes SIN to the FIRST pointer.
                // Previous rounds had sincosf(ang,&cv,&sv) -> cos/sin swapped.
                float cv, sv; sincosf(ang, &sv, &cv);
                float val, other;
                if (job < 1024) {
                    val   = rw[e];
                    other = (c < 64) ? -rw[e+64] : rw[e-64];
                    g_q[(size_t)tok*HCd + e] = val*cv + other*sv;
                } else {
                    const int base = 1024 + h*256;
                    val   = rw[base + c];
                    other = (c < 64) ? -rw[base + c + 64] : rw[base + c - 64];
                    g_k[(size_t)tok*HCd + h*Cd + c] = val*cv + other*sv;
                }
            } else if (job < 3072) {
                const int e = job - 2048;
                const int h = e >> 7, c = e & 127;
                g_v[(size_t)tok*HCd + e] = rw[1024 + h*256 + 128 + c];
            } else if (job < 3136) {
                const int p = job - 3072;           // 0..63  (h*PQK+pq)
                float v0 = rw[3072 + p], v1 = rw[3072+64+p], v2 = rw[3072+128+p];
                float x = R[0]*v0 + R[1]*v1 + R[2]*v2 + T[0];
                float y = R[3]*v0 + R[4]*v1 + R[5]*v2 + T[1];
                float zc= R[6]*v0 + R[7]*v1 + R[8]*v2 + T[2];
                float* dst = g_qpts + ((size_t)tok*Hd + (p>>3))*PQKd*3 + (p&7)*3;
                dst[0]=x; dst[1]=y; dst[2]=zc;
            } else {
                const int p = job - 3136;           // 0..159 (h*20+pp)
                float v0 = rw[3264 + p], v1 = rw[3264+160+p], v2 = rw[3264+320+p];
                float x = R[0]*v0 + R[1]*v1 + R[2]*v2 + T[0];
                float y = R[3]*v0 + R[4]*v1 + R[5]*v2 + T[1];
                float zc= R[6]*v0 + R[7]*v1 + R[8]*v2 + T[2];
                const int h = p/20, pp = p%20;
                if (pp < PQKd) {
                    float* dst = g_kpts + ((size_t)tok*Hd + h)*PQKd*3 + pp*3;
                    dst[0]=x; dst[1]=y; dst[2]=zc;
                } else {
                    float* dst = g_vpts + ((size_t)tok*Hd + h)*PVd*3 + (pp-PQKd)*3;
                    dst[0]=x; dst[1]=y; dst[2]=zc;
                }
            }
        }
    }
}

// ---------------- kernel 2: attention logits + softmax -----------------------
__global__ void k_attn(const float* __restrict__ z,
                       const float* __restrict__ wb, const float* __restrict__ bb,
                       const float* __restrict__ hwraw,
                       const float* __restrict__ mask)
{
    __shared__ float q_s[HCd];
    __shared__ float qp_s[Hd*PQKd*3];
    __shared__ float logits[Hd*Nd];
    __shared__ float z_s[16*CZd];
    __shared__ float hw_s[Hd];

    const int i = blockIdx.x, b = blockIdx.y;
    const int tid = threadIdx.x, lane = tid & 31, h = tid >> 5;
    const int tok = b*Nd + i;

    for (int idx = tid; idx < HCd; idx += 256) q_s[idx]  = g_q[(size_t)tok*HCd + idx];
    for (int idx = tid; idx < 192; idx += 256) qp_s[idx] = g_qpts[(size_t)tok*192 + idx];
    if (tid < Hd) hw_s[tid] = log1pf(expf(hwraw[tid])) * PT_COEF;
    __syncthreads();

    const float mi  = mask[tok];
    const float bbh = bb[h];
    const float4 wbr = ((const float4*)(wb + h*CZd))[lane];
    const float4 qh  = ((const float4*)(q_s + h*Cd))[lane];
    const float hwh  = hw_s[h];

    for (int j0 = 0; j0 < Nd; j0 += 16) {
        __syncthreads();
        {
            const float4* zsrc = (const float4*)(z + ((size_t)tok*Nd + j0)*CZd);
            for (int idx = tid; idx < 16*CZd/4; idx += 256)
                ((float4*)z_s)[idx] = zsrc[idx];
        }
        __syncthreads();
        for (int jj = 0; jj < 16; jj++) {
            const int j = j0 + jj;
            const float4 k4 = ((const float4*)(g_k + ((size_t)(b*Nd+j)*Hd + h)*Cd))[lane];
            const float4 z4 = ((const float4*)(z_s + jj*CZd))[lane];
            float part = QK_SCALE*(qh.x*k4.x + qh.y*k4.y + qh.z*k4.z + qh.w*k4.w)
                       + BIAS_COEF*(z4.x*wbr.x + z4.y*wbr.y + z4.z*wbr.z + z4.w*wbr.w);
            if (lane < 24) {
                float d = qp_s[h*24 + lane] - g_kpts[((size_t)(b*Nd+j)*Hd + h)*24 + lane];
                part -= 0.5f*hwh*d*d;
            }
            #pragma unroll
            for (int off = 16; off; off >>= 1)
                part += __shfl_xor_sync(0xffffffffu, part, off);
            if (lane == 0) {
                float mj = mask[b*Nd + j];
                logits[h*Nd + j] = part + BIAS_COEF*bbh + (mi*mj - 1.0f)*100000.0f;
            }
        }
    }
    __syncthreads();

    // softmax per head (one warp per head)
    float m = -1e30f;
    for (int j = lane; j < Nd; j += 32) m = fmaxf(m, logits[h*Nd + j]);
    #pragma unroll
    for (int off = 16; off; off >>= 1) m = fmaxf(m, __shfl_xor_sync(0xffffffffu, m, off));
    float sum = 0.0f;
    for (int j = lane; j < Nd; j += 32) {
        float e = expf(logits[h*Nd + j] - m);
        logits[h*Nd + j] = e;
        sum += e;
    }
    #pragma unroll
    for (int off = 16; off; off >>= 1) sum += __shfl_xor_sync(0xffffffffu, sum, off);
    const float inv = 1.0f / sum;
    float* arow = g_a + (((size_t)b*Hd + h)*Nd + i)*Nd;
    for (int j = lane; j < Nd; j += 32) arow[j] = logits[h*Nd + j] * inv;
}

// ---------------- kernel 3: weighted sums + inverse rigid + feats ------------
__global__ void k_out(const float* __restrict__ z,
                      const float* __restrict__ rot,
                      const float* __restrict__ trans)
{
    __shared__ float a_s[Hd*Nd];
    __shared__ float opt_s[Hd*PVd*3];
    const int i = blockIdx.x, b = blockIdx.y;
    const int tid = threadIdx.x;
    const int tok = b*Nd + i;

    for (int idx = tid; idx < Hd*Nd; idx += 256) {
        int h = idx >> 9, j = idx & 511;
        a_s[idx] = g_a[(((size_t)b*Hd + h)*Nd + i)*Nd + j];
    }
    __syncthreads();

    float* frow = g_feats + (size_t)tok*FEAT;
    for (int oi = tid; oi < 2336; oi += 256) {
        if (oi < 1024) {                     // o = a @ v
            int h = oi >> 7, c = oi & 127;
            const float* vcol = g_v + (size_t)b*Nd*HCd + h*Cd + c;
            const float* ar = a_s + h*Nd;
            float acc = 0.0f;
            for (int j = 0; j < Nd; j++) acc = fmaf(ar[j], vcol[(size_t)j*HCd], acc);
            frow[oi] = acc;
        } else if (oi < 2048) {              // o_pair = a @ z (row i)
            int e = oi - 1024; int h = e >> 7, c = e & 127;
            const float* zcol = z + (size_t)tok*Nd*CZd + c;
            const float* ar = a_s + h*Nd;
            float acc = 0.0f;
            for (int j = 0; j < Nd; j++) acc = fmaf(ar[j], zcol[(size_t)j*CZd], acc);
            frow[1408 + e] = acc;
        } else {                             // o_pt = a @ v_pts
            int e = oi - 2048;               // h*36 + p*3 + x
            int h = e / 36, r = e % 36;
            const float* vp = g_vpts + (size_t)b*Nd*Hd*PVd*3 + h*36 + r;
            const float* ar = a_s + h*Nd;
            float acc = 0.0f;
            for (int j = 0; j < Nd; j++) acc = fmaf(ar[j], vp[(size_t)j*Hd*36], acc);
            opt_s[e] = acc;
        }
    }
    __syncthreads();

    if (tid < Hd*PVd) {
        const int h = tid / PVd, p = tid % PVd;
        const float* src = opt_s + h*36 + p*3;
        const float* R = rot + tok*9;
        const float* T = trans + tok*3;
        float v0 = src[0]-T[0], v1 = src[1]-T[1], v2 = src[2]-T[2];
        // inverse rotation: out_i = sum_j R[j,i]*v_j
        float x = R[0]*v0 + R[3]*v1 + R[6]*v2;
        float y = R[1]*v0 + R[4]*v1 + R[7]*v2;
        float zc= R[2]*v0 + R[5]*v1 + R[8]*v2;
        const int hp = h*PVd + p;
        frow[1024 + 0*96 + hp] = x;
        frow[1024 + 1*96 + hp] = y;
        frow[1024 + 2*96 + hp] = zc;
        frow[1312 + hp] = sqrtf(x*x + y*y + zc*zc + 1e-8f);
    }
}

// ---------------- kernel 4: output projection --------------------------------
#define TJ4 8
__global__ void k_final(const float* __restrict__ wout,
                        const float* __restrict__ bout,
                        float* __restrict__ out)
{
    extern __shared__ float f_s[];          // TJ4*FEAT
    const int tid  = threadIdx.x;
    const int tok0 = blockIdx.x * TJ4;

    for (int idx = tid; idx < TJ4*FEAT/4; idx += 256)
        ((float4*)f_s)[idx] = ((const float4*)(g_feats + (size_t)tok0*FEAT))[idx];
    __syncthreads();

    const int cs = tid;                     // 256 threads, one output channel each
    float acc[TJ4];
    #pragma unroll
    for (int t = 0; t < TJ4; t++) acc[t] = 0.0f;
    const float* wr = wout + (size_t)cs*FEAT;
    for (int k = 0; k < FEAT; k += 4) {
        float4 w = *(const float4*)(wr + k);
        #pragma unroll
        for (int t = 0; t < TJ4; t++) {
            const float* fp = f_s + t*FEAT + k;
            acc[t] = fmaf(w.x, fp[0], acc[t]);
            acc[t] = fmaf(w.y, fp[1], acc[t]);
            acc[t] = fmaf(w.z, fp[2], acc[t]);
            acc[t] = fmaf(w.w, fp[3], acc[t]);
        }
    }
    const float bv = bout[cs];
    #pragma unroll
    for (int t = 0; t < TJ4; t++) out[(size_t)(tok0+t)*CSd + cs] = acc[t] + bv;
}

// ---------------- launch ------------------------------------------------------
extern "C" void kernel_launch(void* const* d_in, const int* in_sizes, int n_in,
                              void* d_out, int out_size)
{
    const float* s     = (const float*)d_in[0];
    const float* z     = (const float*)d_in[1];
    const float* rot   = (const float*)d_in[2];
    const float* trans = (const float*)d_in[3];
    const float* mask  = (const float*)d_in[4];
    const float* wq    = (const float*)d_in[5];
    const float* bq    = (const float*)d_in[6];
    const float* wkv   = (const float*)d_in[7];
    const float* bkv   = (const float*)d_in[8];
    const float* wqp   = (const float*)d_in[9];
    const float* bqp   = (const float*)d_in[10];
    const float* wkvp  = (const float*)d_in[11];
    const float* bkvp  = (const float*)d_in[12];
    const float* wb    = (const float*)d_in[13];
    const float* bb    = (const float*)d_in[14];
    const float* hw    = (const float*)d_in[15];
    const float* wout  = (const float*)d_in[16];
    const float* bout  = (const float*)d_in[17];

    const int smem1 = (TJ1*CSd + TJ1*NPROJ) * 4;   // 128000 B
    const int smem4 = TJ4*FEAT*4;                  //  77824 B
    cudaFuncSetAttribute(k_proj,  cudaFuncAttributeMaxDynamicSharedMemorySize, smem1);
    cudaFuncSetAttribute(k_final, cudaFuncAttributeMaxDynamicSharedMemorySize, smem4);

    k_proj<<<Bd*Nd/TJ1, 256, smem1>>>(s, rot, trans, wq, bq, wkv, bkv,
                                      wqp, bqp, wkvp, bkvp);
    k_attn<<<dim3(Nd, Bd), 256>>>(z, wb, bb, hw, mask);
    k_out<<<dim3(Nd, Bd), 256>>>(z, rot, trans);
    k_final<<<Bd*Nd/TJ4, 256, smem4>>>(wout, bout, (float*)d_out);
}

// round 15
// speedup vs baseline: 1.2914x; 1.2914x over previous
#include <cuda_runtime.h>
#include <math.h>

#define Bd 2
#define Nd 512
#define CSd 256
#define CZd 128
#define Cd 128
#define Hd 8
#define PQKd 8
#define PVd 12
#define HCd (Hd*Cd)          // 1024
#define NPROJ 3744
#define FEAT 2432

#define QK_SCALE 0.05103103630798287f   // sqrt(1/384)
#define BIAS_COEF 0.5773502691896258f   // sqrt(1/3)
#define PT_COEF 0.09622504486493763f    // sqrt(1/108)

// ---------------- scratch ----------------------------------------------------
__device__ float g_q[Bd*Nd*HCd];
__device__ float g_k[Bd*Nd*HCd];
__device__ float g_v[Bd*Nd*HCd];
__device__ float g_qpts[Bd*Nd*Hd*PQKd*3];
__device__ float g_kpts[Bd*Nd*Hd*PQKd*3];
__device__ float g_vpts[Bd*Nd*Hd*PVd*3];
__device__ float g_a[Bd*Hd*Nd*Nd];       // softmaxed attention [b][h][i][j]
__device__ float g_bias[Bd*Hd*Nd*Nd];    // BIAS_COEF*(z@wb+bb)  [b][h][i][j]
__device__ float g_feats[Bd*Nd*FEAT];
__device__ float g_woutT[FEAT*CSd];      // transposed wout [k][cs]

// ---------------- kernel 1: projections + RoPE + rigid (unchanged) -----------
#define TJ1 8
__global__ void k_proj(const float* __restrict__ s,
                       const float* __restrict__ rot,
                       const float* __restrict__ trans,
                       const float* __restrict__ wq,  const float* __restrict__ bq,
                       const float* __restrict__ wkv, const float* __restrict__ bkv,
                       const float* __restrict__ wqp, const float* __restrict__ bqp,
                       const float* __restrict__ wkvp,const float* __restrict__ bkvp)
{
    extern __shared__ float sh[];
    float* s_s = sh;
    float* raw = sh + TJ1*CSd;
    const int tid  = threadIdx.x;
    const int tok0 = blockIdx.x * TJ1;

    for (int idx = tid; idx < TJ1*CSd/4; idx += 256)
        ((float4*)s_s)[idx] = ((const float4*)(s + (size_t)tok0*CSd))[idx];
    __syncthreads();

    for (int oi = tid; oi < NPROJ; oi += 256) {
        const float* wrow; float bias;
        if (oi < 1024)      { wrow = wq   + oi*CSd;        bias = bq[oi]; }
        else if (oi < 3072) { wrow = wkv  + (oi-1024)*CSd; bias = bkv[oi-1024]; }
        else if (oi < 3264) { wrow = wqp  + (oi-3072)*CSd; bias = bqp[oi-3072]; }
        else                { wrow = wkvp + (oi-3264)*CSd; bias = bkvp[oi-3264]; }
        float acc[TJ1];
        #pragma unroll
        for (int t = 0; t < TJ1; t++) acc[t] = 0.0f;
        const float4* w4 = (const float4*)wrow;
        for (int k4 = 0; k4 < CSd/4; k4++) {
            float4 w = w4[k4];
            #pragma unroll
            for (int t = 0; t < TJ1; t++) {
                const float* sp = s_s + t*CSd + k4*4;
                acc[t] = fmaf(w.x, sp[0], acc[t]);
                acc[t] = fmaf(w.y, sp[1], acc[t]);
                acc[t] = fmaf(w.z, sp[2], acc[t]);
                acc[t] = fmaf(w.w, sp[3], acc[t]);
            }
        }
        #pragma unroll
        for (int t = 0; t < TJ1; t++) raw[t*NPROJ + oi] = acc[t] + bias;
    }
    __syncthreads();

    for (int t = 0; t < TJ1; t++) {
        const int tok = tok0 + t;
        const int n   = tok % Nd;
        const float* R = rot + tok*9;
        const float* T = trans + tok*3;
        const float* rw = raw + t*NPROJ;
        for (int job = tid; job < 3296; job += 256) {
            if (job < 2048) {
                const int e = job & 1023;
                const int h = e >> 7, c = e & 127;
                const int d = c & 63;
                float ang = (float)n * expf(-(float)(2*d) * (9.210340371976184f/128.0f));
                float cv, sv; sincosf(ang, &sv, &cv);   // sin first!
                float val, other;
                if (job < 1024) {
                    val   = rw[e];
                    other = (c < 64) ? -rw[e+64] : rw[e-64];
                    g_q[(size_t)tok*HCd + e] = val*cv + other*sv;
                } else {
                    const int base = 1024 + h*256;
                    val   = rw[base + c];
                    other = (c < 64) ? -rw[base + c + 64] : rw[base + c - 64];
                    g_k[(size_t)tok*HCd + h*Cd + c] = val*cv + other*sv;
                }
            } else if (job < 3072) {
                const int e = job - 2048;
                const int h = e >> 7, c = e & 127;
                g_v[(size_t)tok*HCd + e] = rw[1024 + h*256 + 128 + c];
            } else if (job < 3136) {
                const int p = job - 3072;
                float v0 = rw[3072 + p], v1 = rw[3072+64+p], v2 = rw[3072+128+p];
                float x = R[0]*v0 + R[1]*v1 + R[2]*v2 + T[0];
                float y = R[3]*v0 + R[4]*v1 + R[5]*v2 + T[1];
                float zc= R[6]*v0 + R[7]*v1 + R[8]*v2 + T[2];
                float* dst = g_qpts + ((size_t)tok*Hd + (p>>3))*PQKd*3 + (p&7)*3;
                dst[0]=x; dst[1]=y; dst[2]=zc;
            } else {
                const int p = job - 3136;
                float v0 = rw[3264 + p], v1 = rw[3264+160+p], v2 = rw[3264+320+p];
                float x = R[0]*v0 + R[1]*v1 + R[2]*v2 + T[0];
                float y = R[3]*v0 + R[4]*v1 + R[5]*v2 + T[1];
                float zc= R[6]*v0 + R[7]*v1 + R[8]*v2 + T[2];
                const int h = p/20, pp = p%20;
                if (pp < PQKd) {
                    float* dst = g_kpts + ((size_t)tok*Hd + h)*PQKd*3 + pp*3;
                    dst[0]=x; dst[1]=y; dst[2]=zc;
                } else {
                    float* dst = g_vpts + ((size_t)tok*Hd + h)*PVd*3 + (pp-PQKd)*3;
                    dst[0]=x; dst[1]=y; dst[2]=zc;
                }
            }
        }
    }
}

// ---------------- kernel 2: bias = BIAS_COEF*(z@wb^T + bb) -------------------
__global__ void k_bias(const float* __restrict__ z,
                       const float* __restrict__ wb, const float* __restrict__ bb)
{
    __shared__ float4 wb_s[Hd*32];      // [h][c4]
    __shared__ float4 z_s[32*33];       // [jj][c4] padded stride 33
    __shared__ float  bb_s[Hd];

    const int i = blockIdx.x, b = blockIdx.y;
    const int tid = threadIdx.x;
    const int h = tid >> 5, jj = tid & 31;

    if (tid < Hd*32) wb_s[tid] = ((const float4*)wb)[tid];
    if (tid < Hd) bb_s[tid] = bb[tid];
    __syncthreads();

    const float4* zrow = (const float4*)(z + ((size_t)(b*Nd+i))*Nd*CZd);
    float* brow = g_bias + (((size_t)b*Hd)*Nd + i)*Nd;   // + h*Nd*Nd later

    for (int j0 = 0; j0 < Nd; j0 += 32) {
        __syncthreads();
        for (int idx = tid; idx < 32*32; idx += 256) {
            int r = idx >> 5, c4 = idx & 31;
            z_s[r*33 + c4] = zrow[(size_t)(j0+r)*32 + c4];
        }
        __syncthreads();
        float acc = 0.0f;
        #pragma unroll 8
        for (int c4 = 0; c4 < 32; c4++) {
            float4 zv = z_s[jj*33 + c4];
            float4 wv = wb_s[h*32 + c4];
            acc = fmaf(zv.x, wv.x, acc);
            acc = fmaf(zv.y, wv.y, acc);
            acc = fmaf(zv.z, wv.z, acc);
            acc = fmaf(zv.w, wv.w, acc);
        }
        brow[(size_t)h*Nd*Nd + j0 + jj] = BIAS_COEF * (acc + bb_s[h]);
    }
}

// ---------------- kernel 3: logits + softmax (i-tiled) -----------------------
#define TI 8
__global__ __launch_bounds__(256, 1)
void k_attn2(const float* __restrict__ hwraw, const float* __restrict__ mask)
{
    extern __shared__ float sh[];
    float4* q_s   = (float4*)sh;                    // [h][i][33]  8*8*33 f4 = 8448 f
    float*  qp_s  = sh + 4*(Hd*TI*33);              // [i][192] = 1536 f
    float*  hw_s  = qp_s + TI*192;                  // [8]   (FIX: was TI*24)
    float*  mi_s  = hw_s + Hd;                      // [8]
    float4* k_s   = (float4*)(mi_s + TI);           // [64][33] f4 = 8448 f (16B aligned)
    float*  kp_s  = (float*)(k_s + 64*33);          // [64][25] = 1600 f
    float*  logits= kp_s + 64*25;                   // [8][512] = 4096 f

    const int i0 = blockIdx.x * TI, b = blockIdx.y;
    const int tid = threadIdx.x, lane = tid & 31, w = tid >> 5;

    // stage q (8 tokens x 1024) into padded layout
    for (int idx4 = tid; idx4 < TI*256; idx4 += 256) {
        int i = idx4 >> 8, rem = idx4 & 255, h = rem >> 5, c4 = rem & 31;
        q_s[h*(TI*33) + i*33 + c4] =
            ((const float4*)g_q)[(size_t)(b*Nd + i0 + i)*256 + rem];
    }
    for (int idx = tid; idx < TI*192; idx += 256)
        qp_s[idx] = g_qpts[(size_t)(b*Nd + i0 + idx/192)*192 + idx%192];
    if (tid < Hd) hw_s[tid] = log1pf(expf(hwraw[tid])) * PT_COEF;
    if (tid < TI) mi_s[tid] = mask[b*Nd + i0 + tid];
    __syncthreads();

    const int jloc = tid & 63;       // j within tile
    const int iq   = tid >> 6;       // 0..3 -> handles i = iq, iq+4

    for (int h = 0; h < Hd; h++) {
        const float hwh = hw_s[h];
        for (int j0 = 0; j0 < Nd; j0 += 64) {
            __syncthreads();
            for (int idx4 = tid; idx4 < 64*32; idx4 += 256) {
                int r = idx4 >> 5, c4 = idx4 & 31;
                k_s[r*33 + c4] =
                    ((const float4*)g_k)[(size_t)(b*Nd + j0 + r)*256 + h*32 + c4];
            }
            for (int idx = tid; idx < 64*24; idx += 256) {
                int r = idx/24, t = idx%24;
                kp_s[r*25 + t] = g_kpts[(size_t)(b*Nd + j0 + r)*192 + h*24 + t];
            }
            __syncthreads();

            const float mj = mask[b*Nd + j0 + jloc];
            #pragma unroll
            for (int half = 0; half < 2; half++) {
                const int ii = iq + half*4;
                float qk = 0.0f;
                #pragma unroll 8
                for (int c4 = 0; c4 < 32; c4++) {
                    float4 qv = q_s[h*(TI*33) + ii*33 + c4];
                    float4 kv = k_s[jloc*33 + c4];
                    qk = fmaf(qv.x, kv.x, qk);
                    qk = fmaf(qv.y, kv.y, qk);
                    qk = fmaf(qv.z, kv.z, qk);
                    qk = fmaf(qv.w, kv.w, qk);
                }
                float d2 = 0.0f;
                const float* qp = qp_s + ii*192 + h*24;
                const float* kp = kp_s + jloc*25;
                #pragma unroll
                for (int t = 0; t < 24; t++) {
                    float d = qp[t] - kp[t];
                    d2 = fmaf(d, d, d2);
                }
                float bias_v = g_bias[(((size_t)b*Hd + h)*Nd + i0 + ii)*Nd + j0 + jloc];
                float lg = QK_SCALE*qk + bias_v - 0.5f*hwh*d2
                         + (mi_s[ii]*mj - 1.0f)*100000.0f;
                logits[ii*Nd + j0 + jloc] = lg;
            }
        }
        __syncthreads();
        // softmax: warp w -> row i=w
        {
            float* row = logits + w*Nd;
            float m = -1e30f;
            for (int j = lane; j < Nd; j += 32) m = fmaxf(m, row[j]);
            #pragma unroll
            for (int off = 16; off; off >>= 1) m = fmaxf(m, __shfl_xor_sync(0xffffffffu, m, off));
            float sum = 0.0f;
            for (int j = lane; j < Nd; j += 32) {
                float e = expf(row[j] - m);
                row[j] = e;
                sum += e;
            }
            #pragma unroll
            for (int off = 16; off; off >>= 1) sum += __shfl_xor_sync(0xffffffffu, sum, off);
            const float inv = 1.0f/sum;
            float* arow = g_a + (((size_t)b*Hd + h)*Nd + i0 + w)*Nd;
            for (int j = lane; j < Nd; j += 32) arow[j] = row[j]*inv;
        }
        __syncthreads();
    }
}

// ---------------- kernel 4: fused a@{v,z,vpts} + inverse rigid ---------------
#define TJO 16
__global__ __launch_bounds__(256, 1)
void k_out2(const float* __restrict__ z,
            const float* __restrict__ rot,
            const float* __restrict__ trans)
{
    extern __shared__ float sh[];
    float4* v_s   = (float4*)sh;                       // [16j][256]  16384 f
    float4* z_s   = (float4*)(sh + 4*TJO*256);         // [8i][16j][32] 16384 f
    float*  vp_s  = sh + 4*TJO*256 + 4*TI*TJO*32;      // [16j][288] 4608 f
    float*  a_s   = vp_s + TJO*288;                    // [8i][8h][16j] 1024 f
    float*  opt_s = sh;                                // alias v_s after sync

    const int i0 = blockIdx.x * TI, b = blockIdx.y;
    const int tid = threadIdx.x, lane = tid & 31, w = tid >> 5;
    const int iw = i0 + w;                              // this warp's query

    float4 o_acc[Hd];
    float4 zp_acc[Hd];
    float  pt_acc[9];
    #pragma unroll
    for (int h = 0; h < Hd; h++) {
        o_acc[h]  = make_float4(0.f,0.f,0.f,0.f);
        zp_acc[h] = make_float4(0.f,0.f,0.f,0.f);
    }
    #pragma unroll
    for (int t = 0; t < 9; t++) pt_acc[t] = 0.0f;

    for (int j0 = 0; j0 < Nd; j0 += TJO) {
        __syncthreads();
        for (int idx4 = tid; idx4 < TJO*256; idx4 += 256) {
            int r = idx4 >> 8, c4 = idx4 & 255;
            v_s[r*256 + c4] = ((const float4*)g_v)[(size_t)(b*Nd + j0 + r)*256 + c4];
        }
        for (int idx4 = tid; idx4 < TI*TJO*32; idx4 += 256) {
            int i = idx4 >> 9, r = (idx4 >> 5) & 15, c4 = idx4 & 31;
            z_s[i*(TJO*32) + r*32 + c4] =
                ((const float4*)z)[((size_t)(b*Nd + i0 + i)*Nd + j0 + r)*32 + c4];
        }
        for (int idx = tid; idx < TJO*288; idx += 256) {
            int r = idx/288, t = idx%288;
            vp_s[r*288 + t] = g_vpts[(size_t)(b*Nd + j0 + r)*288 + t];
        }
        for (int idx = tid; idx < TI*Hd*TJO; idx += 256) {
            int i = idx >> 7, h = (idx >> 4) & 7, jj = idx & 15;
            a_s[(i*Hd + h)*TJO + jj] =
                g_a[(((size_t)b*Hd + h)*Nd + i0 + i)*Nd + j0 + jj];
        }
        __syncthreads();

        for (int jj = 0; jj < TJO; jj++) {
            float av[Hd];
            #pragma unroll
            for (int h = 0; h < Hd; h++) av[h] = a_s[(w*Hd + h)*TJO + jj];
            float4 z4 = z_s[w*(TJO*32) + jj*32 + lane];
            #pragma unroll
            for (int h = 0; h < Hd; h++) {
                float4 v4 = v_s[jj*256 + h*32 + lane];
                o_acc[h].x  = fmaf(av[h], v4.x, o_acc[h].x);
                o_acc[h].y  = fmaf(av[h], v4.y, o_acc[h].y);
                o_acc[h].z  = fmaf(av[h], v4.z, o_acc[h].z);
                o_acc[h].w  = fmaf(av[h], v4.w, o_acc[h].w);
                zp_acc[h].x = fmaf(av[h], z4.x, zp_acc[h].x);
                zp_acc[h].y = fmaf(av[h], z4.y, zp_acc[h].y);
                zp_acc[h].z = fmaf(av[h], z4.z, zp_acc[h].z);
                zp_acc[h].w = fmaf(av[h], z4.w, zp_acc[h].w);
            }
            #pragma unroll
            for (int t = 0; t < 9; t++) {
                int r = lane + 32*t;           // < 288
                int ht = r/36;
                float aval = a_s[(w*Hd + ht)*TJO + jj];
                pt_acc[t] = fmaf(aval, vp_s[jj*288 + r], pt_acc[t]);
            }
        }
    }

    // write o and o_pair (register-resident; no smem dependency)
    {
        const int tok = b*Nd + iw;
        float4* frow4 = (float4*)(g_feats + (size_t)tok*FEAT);
        #pragma unroll
        for (int h = 0; h < Hd; h++) {
            frow4[h*32 + lane]       = o_acc[h];           // o at [0,1024)
            frow4[352 + h*32 + lane] = zp_acc[h];          // o_pair at [1408,2432)
        }
    }
    __syncthreads();              // all warps done with v_s/z_s
    #pragma unroll
    for (int t = 0; t < 9; t++) opt_s[w*288 + lane + 32*t] = pt_acc[t];
    __syncthreads();

    // inverse rigid + norms: 8i * 96(hp) jobs
    for (int idx = tid; idx < TI*96; idx += 256) {
        const int i = idx/96, hp = idx%96;
        const int h = hp/PVd, p = hp%PVd;
        const int tok = b*Nd + i0 + i;
        const float* src = opt_s + i*288 + h*36 + p*3;
        const float* R = rot + tok*9;
        const float* T = trans + tok*3;
        float v0 = src[0]-T[0], v1 = src[1]-T[1], v2 = src[2]-T[2];
        float x = R[0]*v0 + R[3]*v1 + R[6]*v2;
        float y = R[1]*v0 + R[4]*v1 + R[7]*v2;
        float zc= R[2]*v0 + R[5]*v1 + R[8]*v2;
        float* frow = g_feats + (size_t)tok*FEAT;
        frow[1024 + hp]       = x;
        frow[1024 + 96 + hp]  = y;
        frow[1024 + 192 + hp] = zc;
        frow[1312 + hp] = sqrtf(x*x + y*y + zc*zc + 1e-8f);
    }
}

// ---------------- kernel 5a: transpose wout ----------------------------------
__global__ void k_trans(const float* __restrict__ wout)
{
    __shared__ float tile[32][33];
    const int k0 = blockIdx.x*32, c0 = blockIdx.y*32;
    const int tx = threadIdx.x & 31, ty = threadIdx.x >> 5;   // 32x8
    #pragma unroll
    for (int r = 0; r < 32; r += 8)
        tile[ty+r][tx] = wout[(size_t)(c0+ty+r)*FEAT + k0 + tx];
    __syncthreads();
    #pragma unroll
    for (int r = 0; r < 32; r += 8)
        g_woutT[(size_t)(k0+ty+r)*CSd + c0 + tx] = tile[tx][ty+r];
}

// ---------------- kernel 5b: output projection (coalesced) -------------------
#define TJ4 8
__global__ __launch_bounds__(256, 1)
void k_final2(const float* __restrict__ bout, float* __restrict__ out)
{
    extern __shared__ float f_s[];          // TJ4*FEAT
    const int tid  = threadIdx.x;
    const int tok0 = blockIdx.x * TJ4;

    for (int idx = tid; idx < TJ4*FEAT/4; idx += 256)
        ((float4*)f_s)[idx] = ((const float4*)(g_feats + (size_t)tok0*FEAT))[idx];
    __syncthreads();

    const int cs = tid;
    float acc[TJ4];
    #pragma unroll
    for (int t = 0; t < TJ4; t++) acc[t] = 0.0f;
    for (int k = 0; k < FEAT; k++) {
        float w = g_woutT[(size_t)k*CSd + cs];      // coalesced across threads
        #pragma unroll
        for (int t = 0; t < TJ4; t++)
            acc[t] = fmaf(w, f_s[t*FEAT + k], acc[t]);
    }
    const float bv = bout[cs];
    #pragma unroll
    for (int t = 0; t < TJ4; t++) out[(size_t)(tok0+t)*CSd + cs] = acc[t] + bv;
}

// ---------------- launch ------------------------------------------------------
extern "C" void kernel_launch(void* const* d_in, const int* in_sizes, int n_in,
                              void* d_out, int out_size)
{
    const float* s     = (const float*)d_in[0];
    const float* z     = (const float*)d_in[1];
    const float* rot   = (const float*)d_in[2];
    const float* trans = (const float*)d_in[3];
    const float* mask  = (const float*)d_in[4];
    const float* wq    = (const float*)d_in[5];
    const float* bq    = (const float*)d_in[6];
    const float* wkv   = (const float*)d_in[7];
    const float* bkv   = (const float*)d_in[8];
    const float* wqp   = (const float*)d_in[9];
    const float* bqp   = (const float*)d_in[10];
    const float* wkvp  = (const float*)d_in[11];
    const float* bkvp  = (const float*)d_in[12];
    const float* wb    = (const float*)d_in[13];
    const float* bb    = (const float*)d_in[14];
    const float* hw    = (const float*)d_in[15];
    const float* wout  = (const float*)d_in[16];
    const float* bout  = (const float*)d_in[17];

    const int smem1 = (TJ1*CSd + TJ1*NPROJ) * 4;                    // 128000
    // k_attn2: q_s 8448 + qp 1536 + hw 8 + mi 8 + k_s 8448 + kp 1600 + logits 4096
    const int smemA = (4*(Hd*TI*33) + TI*192 + Hd + TI
                      + 4*(64*33) + 64*25 + TI*Nd) * 4;             // 96576
    // k_out2: v_s 16384 + z_s 16384 + vp 4608 + a 1024
    const int smemO = (4*TJO*256 + 4*TI*TJO*32 + TJO*288 + TI*Hd*TJO) * 4; // 153600
    const int smem4 = TJ4*FEAT*4;                                   // 77824

    cudaFuncSetAttribute(k_proj,   cudaFuncAttributeMaxDynamicSharedMemorySize, smem1);
    cudaFuncSetAttribute(k_attn2,  cudaFuncAttributeMaxDynamicSharedMemorySize, smemA);
    cudaFuncSetAttribute(k_out2,   cudaFuncAttributeMaxDynamicSharedMemorySize, smemO);
    cudaFuncSetAttribute(k_final2, cudaFuncAttributeMaxDynamicSharedMemorySize, smem4);

    k_trans<<<dim3(FEAT/32, CSd/32), 256>>>(wout);
    k_proj<<<Bd*Nd/TJ1, 256, smem1>>>(s, rot, trans, wq, bq, wkv, bkv,
                                      wqp, bqp, wkvp, bkvp);
    k_bias<<<dim3(Nd, Bd), 256>>>(z, wb, bb);
    k_attn2<<<dim3(Nd/TI, Bd), 256, smemA>>>(hw, mask);
    k_out2<<<dim3(Nd/TI, Bd), 256, smemO>>>(z, rot, trans);
    k_final2<<<Bd*Nd/TJ4, 256, smem4>>>(bout, (float*)d_out);
}

// round 16
// speedup vs baseline: 1.4609x; 1.1312x over previous
#include <cuda_runtime.h>
#include <math.h>

#define Bd 2
#define Nd 512
#define CSd 256
#define CZd 128
#define Cd 128
#define Hd 8
#define PQKd 8
#define PVd 12
#define HCd (Hd*Cd)          // 1024
#define NPROJ 3744
#define FEAT 2432

#define QK_SCALE 0.05103103630798287f   // sqrt(1/384)
#define BIAS_COEF 0.5773502691896258f   // sqrt(1/3)
#define PT_COEF 0.09622504486493763f    // sqrt(1/108)

// ---------------- scratch ----------------------------------------------------
__device__ float g_q[Bd*Nd*HCd];
__device__ float g_k[Bd*Nd*HCd];
__device__ float g_v[Bd*Nd*HCd];
__device__ float g_qpts[Bd*Nd*Hd*PQKd*3];
__device__ float g_kpts[Bd*Nd*Hd*PQKd*3];
__device__ float g_vpts[Bd*Nd*Hd*PVd*3];
__device__ float g_a[Bd*Hd*Nd*Nd];       // softmaxed attention [b][h][i][j]
__device__ float g_bias[Bd*Hd*Nd*Nd];    // BIAS_COEF*(z@wb+bb)  [b][h][i][j]
__device__ float g_feats[Bd*Nd*FEAT];
__device__ float g_woutT[FEAT*CSd];      // transposed wout [k][cs]

// ---------------- kernel 1: projections + RoPE + rigid (unchanged) -----------
#define TJ1 8
__global__ void k_proj(const float* __restrict__ s,
                       const float* __restrict__ rot,
                       const float* __restrict__ trans,
                       const float* __restrict__ wq,  const float* __restrict__ bq,
                       const float* __restrict__ wkv, const float* __restrict__ bkv,
                       const float* __restrict__ wqp, const float* __restrict__ bqp,
                       const float* __restrict__ wkvp,const float* __restrict__ bkvp)
{
    extern __shared__ float sh[];
    float* s_s = sh;
    float* raw = sh + TJ1*CSd;
    const int tid  = threadIdx.x;
    const int tok0 = blockIdx.x * TJ1;

    for (int idx = tid; idx < TJ1*CSd/4; idx += 256)
        ((float4*)s_s)[idx] = ((const float4*)(s + (size_t)tok0*CSd))[idx];
    __syncthreads();

    for (int oi = tid; oi < NPROJ; oi += 256) {
        const float* wrow; float bias;
        if (oi < 1024)      { wrow = wq   + oi*CSd;        bias = bq[oi]; }
        else if (oi < 3072) { wrow = wkv  + (oi-1024)*CSd; bias = bkv[oi-1024]; }
        else if (oi < 3264) { wrow = wqp  + (oi-3072)*CSd; bias = bqp[oi-3072]; }
        else                { wrow = wkvp + (oi-3264)*CSd; bias = bkvp[oi-3264]; }
        float acc[TJ1];
        #pragma unroll
        for (int t = 0; t < TJ1; t++) acc[t] = 0.0f;
        const float4* w4 = (const float4*)wrow;
        for (int k4 = 0; k4 < CSd/4; k4++) {
            float4 w = w4[k4];
            #pragma unroll
            for (int t = 0; t < TJ1; t++) {
                const float* sp = s_s + t*CSd + k4*4;
                acc[t] = fmaf(w.x, sp[0], acc[t]);
                acc[t] = fmaf(w.y, sp[1], acc[t]);
                acc[t] = fmaf(w.z, sp[2], acc[t]);
                acc[t] = fmaf(w.w, sp[3], acc[t]);
            }
        }
        #pragma unroll
        for (int t = 0; t < TJ1; t++) raw[t*NPROJ + oi] = acc[t] + bias;
    }
    __syncthreads();

    for (int t = 0; t < TJ1; t++) {
        const int tok = tok0 + t;
        const int n   = tok % Nd;
        const float* R = rot + tok*9;
        const float* T = trans + tok*3;
        const float* rw = raw + t*NPROJ;
        for (int job = tid; job < 3296; job += 256) {
            if (job < 2048) {
                const int e = job & 1023;
                const int h = e >> 7, c = e & 127;
                const int d = c & 63;
                float ang = (float)n * expf(-(float)(2*d) * (9.210340371976184f/128.0f));
                float cv, sv; sincosf(ang, &sv, &cv);   // sin first!
                float val, other;
                if (job < 1024) {
                    val   = rw[e];
                    other = (c < 64) ? -rw[e+64] : rw[e-64];
                    g_q[(size_t)tok*HCd + e] = val*cv + other*sv;
                } else {
                    const int base = 1024 + h*256;
                    val   = rw[base + c];
                    other = (c < 64) ? -rw[base + c + 64] : rw[base + c - 64];
                    g_k[(size_t)tok*HCd + h*Cd + c] = val*cv + other*sv;
                }
            } else if (job < 3072) {
                const int e = job - 2048;
                const int h = e >> 7, c = e & 127;
                g_v[(size_t)tok*HCd + e] = rw[1024 + h*256 + 128 + c];
            } else if (job < 3136) {
                const int p = job - 3072;
                float v0 = rw[3072 + p], v1 = rw[3072+64+p], v2 = rw[3072+128+p];
                float x = R[0]*v0 + R[1]*v1 + R[2]*v2 + T[0];
                float y = R[3]*v0 + R[4]*v1 + R[5]*v2 + T[1];
                float zc= R[6]*v0 + R[7]*v1 + R[8]*v2 + T[2];
                float* dst = g_qpts + ((size_t)tok*Hd + (p>>3))*PQKd*3 + (p&7)*3;
                dst[0]=x; dst[1]=y; dst[2]=zc;
            } else {
                const int p = job - 3136;
                float v0 = rw[3264 + p], v1 = rw[3264+160+p], v2 = rw[3264+320+p];
                float x = R[0]*v0 + R[1]*v1 + R[2]*v2 + T[0];
                float y = R[3]*v0 + R[4]*v1 + R[5]*v2 + T[1];
                float zc= R[6]*v0 + R[7]*v1 + R[8]*v2 + T[2];
                const int h = p/20, pp = p%20;
                if (pp < PQKd) {
                    float* dst = g_kpts + ((size_t)tok*Hd + h)*PQKd*3 + pp*3;
                    dst[0]=x; dst[1]=y; dst[2]=zc;
                } else {
                    float* dst = g_vpts + ((size_t)tok*Hd + h)*PVd*3 + (pp-PQKd)*3;
                    dst[0]=x; dst[1]=y; dst[2]=zc;
                }
            }
        }
    }
}

// ---------------- kernel 2: bias = BIAS_COEF*(z@wb^T + bb) -------------------
__global__ void k_bias(const float* __restrict__ z,
                       const float* __restrict__ wb, const float* __restrict__ bb)
{
    __shared__ float4 wb_s[Hd*32];      // [h][c4]
    __shared__ float4 z_s[32*33];       // [jj][c4] padded stride 33
    __shared__ float  bb_s[Hd];

    const int i = blockIdx.x, b = blockIdx.y;
    const int tid = threadIdx.x;
    const int h = tid >> 5, jj = tid & 31;

    if (tid < Hd*32) wb_s[tid] = ((const float4*)wb)[tid];
    if (tid < Hd) bb_s[tid] = bb[tid];
    __syncthreads();

    const float4* zrow = (const float4*)(z + ((size_t)(b*Nd+i))*Nd*CZd);
    float* brow = g_bias + (((size_t)b*Hd)*Nd + i)*Nd;   // + h*Nd*Nd later

    for (int j0 = 0; j0 < Nd; j0 += 32) {
        __syncthreads();
        for (int idx = tid; idx < 32*32; idx += 256) {
            int r = idx >> 5, c4 = idx & 31;
            z_s[r*33 + c4] = zrow[(size_t)(j0+r)*32 + c4];
        }
        __syncthreads();
        float acc = 0.0f;
        #pragma unroll 8
        for (int c4 = 0; c4 < 32; c4++) {
            float4 zv = z_s[jj*33 + c4];
            float4 wv = wb_s[h*32 + c4];
            acc = fmaf(zv.x, wv.x, acc);
            acc = fmaf(zv.y, wv.y, acc);
            acc = fmaf(zv.z, wv.z, acc);
            acc = fmaf(zv.w, wv.w, acc);
        }
        brow[(size_t)h*Nd*Nd + j0 + jj] = BIAS_COEF * (acc + bb_s[h]);
    }
}

// ---------------- kernel 3: logits + softmax (i-tiled, h-split, ILP) ---------
#define TI 8
#define HG 2                 // heads per block
__global__ __launch_bounds__(256)
void k_attn3(const float* __restrict__ hwraw, const float* __restrict__ mask)
{
    extern __shared__ float sh[];
    // layout (floats): q_s[2112] | k_s[8448] | qp_s[384] | hw[2] | mi[8] |
    //                  kp_s[1600] | logits[8192]
    float4* q_s   = (float4*)sh;                       // [hh][i][33] f4
    float4* k_s   = (float4*)(sh + 2112);              // [64][33] f4
    float*  qp_s  = sh + 2112 + 8448;                  // [i][48]
    float*  hw_s  = qp_s + TI*48;                      // [2]
    float*  mi_s  = hw_s + HG;                         // [8]
    float*  kp_s  = mi_s + TI;                         // [64][25]
    float*  logits= kp_s + 64*25;                      // [hh][i][512]

    const int i0 = blockIdx.x * TI;
    const int h0 = blockIdx.y * HG;
    const int b  = blockIdx.z;
    const int tid = threadIdx.x, lane = tid & 31, w = tid >> 5;

    for (int idx4 = tid; idx4 < HG*TI*32; idx4 += 256) {
        int hh = idx4 >> 8, i = (idx4 >> 5) & 7, c4 = idx4 & 31;
        q_s[hh*(TI*33) + i*33 + c4] =
            ((const float4*)g_q)[(size_t)(b*Nd + i0 + i)*256 + (h0+hh)*32 + c4];
    }
    for (int idx = tid; idx < TI*48; idx += 256) {
        int i = idx/48, t = idx%48, hh = t/24, tt = t%24;
        qp_s[i*48 + t] = g_qpts[(size_t)(b*Nd + i0 + i)*192 + (h0+hh)*24 + tt];
    }
    if (tid < HG) hw_s[tid] = log1pf(expf(hwraw[h0+tid])) * PT_COEF;
    if (tid < TI) mi_s[tid] = mask[b*Nd + i0 + tid];
    __syncthreads();

    const int jloc = tid & 63;
    const int iq   = tid >> 6;

    for (int hh = 0; hh < HG; hh++) {
        const int h = h0 + hh;
        const float hwh = hw_s[hh];
        for (int j0 = 0; j0 < Nd; j0 += 64) {
            __syncthreads();
            for (int idx4 = tid; idx4 < 64*32; idx4 += 256) {
                int r = idx4 >> 5, c4 = idx4 & 31;
                k_s[r*33 + c4] =
                    ((const float4*)g_k)[(size_t)(b*Nd + j0 + r)*256 + h*32 + c4];
            }
            for (int idx = tid; idx < 64*24; idx += 256) {
                int r = idx/24, t = idx%24;
                kp_s[r*25 + t] = g_kpts[(size_t)(b*Nd + j0 + r)*192 + h*24 + t];
            }
            __syncthreads();

            const float mj = mask[b*Nd + j0 + jloc];
            #pragma unroll
            for (int half = 0; half < 2; half++) {
                const int ii = iq + half*4;
                const float4* qv = q_s + hh*(TI*33) + ii*33;
                const float4* kv = k_s + jloc*33;
                // 4 independent accumulator chains
                float a0=0.f, a1=0.f, a2=0.f, a3=0.f;
                #pragma unroll
                for (int c4 = 0; c4 < 32; c4 += 4) {
                    float4 q0 = qv[c4+0], k0 = kv[c4+0];
                    float4 q1 = qv[c4+1], k1 = kv[c4+1];
                    float4 q2 = qv[c4+2], k2 = kv[c4+2];
                    float4 q3 = qv[c4+3], k3 = kv[c4+3];
                    a0 = fmaf(q0.x,k0.x, fmaf(q0.y,k0.y, fmaf(q0.z,k0.z, fmaf(q0.w,k0.w, a0))));
                    a1 = fmaf(q1.x,k1.x, fmaf(q1.y,k1.y, fmaf(q1.z,k1.z, fmaf(q1.w,k1.w, a1))));
                    a2 = fmaf(q2.x,k2.x, fmaf(q2.y,k2.y, fmaf(q2.z,k2.z, fmaf(q2.w,k2.w, a2))));
                    a3 = fmaf(q3.x,k3.x, fmaf(q3.y,k3.y, fmaf(q3.z,k3.z, fmaf(q3.w,k3.w, a3))));
                }
                float qk = (a0 + a1) + (a2 + a3);
                // pt term: 3 independent chains over 24 dims
                const float* qp = qp_s + ii*48 + hh*24;
                const float* kp = kp_s + jloc*25;
                float d0=0.f, d1=0.f, d2a=0.f;
                #pragma unroll
                for (int t = 0; t < 8; t++) {
                    float u0 = qp[t]      - kp[t];
                    float u1 = qp[t+8]    - kp[t+8];
                    float u2 = qp[t+16]   - kp[t+16];
                    d0 = fmaf(u0, u0, d0);
                    d1 = fmaf(u1, u1, d1);
                    d2a= fmaf(u2, u2, d2a);
                }
                float d2 = (d0 + d1) + d2a;
                float bias_v = g_bias[(((size_t)b*Hd + h)*Nd + i0 + ii)*Nd + j0 + jloc];
                float lg = QK_SCALE*qk + bias_v - 0.5f*hwh*d2
                         + (mi_s[ii]*mj - 1.0f)*100000.0f;
                logits[(hh*TI + ii)*Nd + j0 + jloc] = lg;
            }
        }
    }
    __syncthreads();

    // softmax: 16 rows (hh,i), 8 warps -> 2 rows per warp
    for (int r = w; r < HG*TI; r += 8) {
        const int hh = r >> 3, ii = r & 7;
        float* row = logits + r*Nd;
        float m = -1e30f;
        for (int j = lane; j < Nd; j += 32) m = fmaxf(m, row[j]);
        #pragma unroll
        for (int off = 16; off; off >>= 1) m = fmaxf(m, __shfl_xor_sync(0xffffffffu, m, off));
        float sum = 0.0f;
        for (int j = lane; j < Nd; j += 32) {
            float e = expf(row[j] - m);
            row[j] = e;
            sum += e;
        }
        #pragma unroll
        for (int off = 16; off; off >>= 1) sum += __shfl_xor_sync(0xffffffffu, sum, off);
        const float inv = 1.0f/sum;
        float* arow = g_a + (((size_t)b*Hd + h0 + hh)*Nd + i0 + ii)*Nd;
        for (int j = lane; j < Nd; j += 32) arow[j] = row[j]*inv;
    }
}

// ---------------- kernel 4: fused a@{v,z,vpts} + inverse rigid ---------------
#define TJO 16
__global__ __launch_bounds__(256, 1)
void k_out2(const float* __restrict__ z,
            const float* __restrict__ rot,
            const float* __restrict__ trans)
{
    extern __shared__ float sh[];
    float4* v_s   = (float4*)sh;                       // [16j][256]  16384 f
    float4* z_s   = (float4*)(sh + 4*TJO*256);         // [8i][16j][32] 16384 f
    float*  vp_s  = sh + 4*TJO*256 + 4*TI*TJO*32;      // [16j][288] 4608 f
    float*  a_s   = vp_s + TJO*288;                    // [8i][8h][16j] 1024 f
    float*  opt_s = sh;                                // alias v_s after sync

    const int i0 = blockIdx.x * TI, b = blockIdx.y;
    const int tid = threadIdx.x, lane = tid & 31, w = tid >> 5;
    const int iw = i0 + w;                              // this warp's query

    float4 o_acc[Hd];
    float4 zp_acc[Hd];
    float  pt_acc[9];
    #pragma unroll
    for (int h = 0; h < Hd; h++) {
        o_acc[h]  = make_float4(0.f,0.f,0.f,0.f);
        zp_acc[h] = make_float4(0.f,0.f,0.f,0.f);
    }
    #pragma unroll
    for (int t = 0; t < 9; t++) pt_acc[t] = 0.0f;

    for (int j0 = 0; j0 < Nd; j0 += TJO) {
        __syncthreads();
        for (int idx4 = tid; idx4 < TJO*256; idx4 += 256) {
            int r = idx4 >> 8, c4 = idx4 & 255;
            v_s[r*256 + c4] = ((const float4*)g_v)[(size_t)(b*Nd + j0 + r)*256 + c4];
        }
        for (int idx4 = tid; idx4 < TI*TJO*32; idx4 += 256) {
            int i = idx4 >> 9, r = (idx4 >> 5) & 15, c4 = idx4 & 31;
            z_s[i*(TJO*32) + r*32 + c4] =
                ((const float4*)z)[((size_t)(b*Nd + i0 + i)*Nd + j0 + r)*32 + c4];
        }
        for (int idx = tid; idx < TJO*288; idx += 256) {
            int r = idx/288, t = idx%288;
            vp_s[r*288 + t] = g_vpts[(size_t)(b*Nd + j0 + r)*288 + t];
        }
        for (int idx = tid; idx < TI*Hd*TJO; idx += 256) {
            int i = idx >> 7, h = (idx >> 4) & 7, jj = idx & 15;
            a_s[(i*Hd + h)*TJO + jj] =
                g_a[(((size_t)b*Hd + h)*Nd + i0 + i)*Nd + j0 + jj];
        }
        __syncthreads();

        for (int jj = 0; jj < TJO; jj++) {
            float av[Hd];
            #pragma unroll
            for (int h = 0; h < Hd; h++) av[h] = a_s[(w*Hd + h)*TJO + jj];
            float4 z4 = z_s[w*(TJO*32) + jj*32 + lane];
            #pragma unroll
            for (int h = 0; h < Hd; h++) {
                float4 v4 = v_s[jj*256 + h*32 + lane];
                o_acc[h].x  = fmaf(av[h], v4.x, o_acc[h].x);
                o_acc[h].y  = fmaf(av[h], v4.y, o_acc[h].y);
                o_acc[h].z  = fmaf(av[h], v4.z, o_acc[h].z);
                o_acc[h].w  = fmaf(av[h], v4.w, o_acc[h].w);
                zp_acc[h].x = fmaf(av[h], z4.x, zp_acc[h].x);
                zp_acc[h].y = fmaf(av[h], z4.y, zp_acc[h].y);
                zp_acc[h].z = fmaf(av[h], z4.z, zp_acc[h].z);
                zp_acc[h].w = fmaf(av[h], z4.w, zp_acc[h].w);
            }
            #pragma unroll
            for (int t = 0; t < 9; t++) {
                int r = lane + 32*t;           // < 288
                int ht = r/36;
                float aval = a_s[(w*Hd + ht)*TJO + jj];
                pt_acc[t] = fmaf(aval, vp_s[jj*288 + r], pt_acc[t]);
            }
        }
    }

    // write o and o_pair (register-resident; no smem dependency)
    {
        const int tok = b*Nd + iw;
        float4* frow4 = (float4*)(g_feats + (size_t)tok*FEAT);
        #pragma unroll
        for (int h = 0; h < Hd; h++) {
            frow4[h*32 + lane]       = o_acc[h];           // o at [0,1024)
            frow4[352 + h*32 + lane] = zp_acc[h];          // o_pair at [1408,2432)
        }
    }
    __syncthreads();              // all warps done with v_s/z_s
    #pragma unroll
    for (int t = 0; t < 9; t++) opt_s[w*288 + lane + 32*t] = pt_acc[t];
    __syncthreads();

    // inverse rigid + norms: 8i * 96(hp) jobs
    for (int idx = tid; idx < TI*96; idx += 256) {
        const int i = idx/96, hp = idx%96;
        const int h = hp/PVd, p = hp%PVd;
        const int tok = b*Nd + i0 + i;
        const float* src = opt_s + i*288 + h*36 + p*3;
        const float* R = rot + tok*9;
        const float* T = trans + tok*3;
        float v0 = src[0]-T[0], v1 = src[1]-T[1], v2 = src[2]-T[2];
        float x = R[0]*v0 + R[3]*v1 + R[6]*v2;
        float y = R[1]*v0 + R[4]*v1 + R[7]*v2;
        float zc= R[2]*v0 + R[5]*v1 + R[8]*v2;
        float* frow = g_feats + (size_t)tok*FEAT;
        frow[1024 + hp]       = x;
        frow[1024 + 96 + hp]  = y;
        frow[1024 + 192 + hp] = zc;
        frow[1312 + hp] = sqrtf(x*x + y*y + zc*zc + 1e-8f);
    }
}

// ---------------- kernel 5a: transpose wout ----------------------------------
__global__ void k_trans(const float* __restrict__ wout)
{
    __shared__ float tile[32][33];
    const int k0 = blockIdx.x*32, c0 = blockIdx.y*32;
    const int tx = threadIdx.x & 31, ty = threadIdx.x >> 5;   // 32x8
    #pragma unroll
    for (int r = 0; r < 32; r += 8)
        tile[ty+r][tx] = wout[(size_t)(c0+ty+r)*FEAT + k0 + tx];
    __syncthreads();
    #pragma unroll
    for (int r = 0; r < 32; r += 8)
        g_woutT[(size_t)(k0+ty+r)*CSd + c0 + tx] = tile[tx][ty+r];
}

// ---------------- kernel 5b: output projection (coalesced) -------------------
#define TJ4 8
__global__ __launch_bounds__(256, 1)
void k_final2(const float* __restrict__ bout, float* __restrict__ out)
{
    extern __shared__ float f_s[];          // TJ4*FEAT
    const int tid  = threadIdx.x;
    const int tok0 = blockIdx.x * TJ4;

    for (int idx = tid; idx < TJ4*FEAT/4; idx += 256)
        ((float4*)f_s)[idx] = ((const float4*)(g_feats + (size_t)tok0*FEAT))[idx];
    __syncthreads();

    const int cs = tid;
    float acc[TJ4];
    #pragma unroll
    for (int t = 0; t < TJ4; t++) acc[t] = 0.0f;
    for (int k = 0; k < FEAT; k++) {
        float w = g_woutT[(size_t)k*CSd + cs];      // coalesced across threads
        #pragma unroll
        for (int t = 0; t < TJ4; t++)
            acc[t] = fmaf(w, f_s[t*FEAT + k], acc[t]);
    }
    const float bv = bout[cs];
    #pragma unroll
    for (int t = 0; t < TJ4; t++) out[(size_t)(tok0+t)*CSd + cs] = acc[t] + bv;
}

// ---------------- launch ------------------------------------------------------
extern "C" void kernel_launch(void* const* d_in, const int* in_sizes, int n_in,
                              void* d_out, int out_size)
{
    const float* s     = (const float*)d_in[0];
    const float* z     = (const float*)d_in[1];
    const float* rot   = (const float*)d_in[2];
    const float* trans = (const float*)d_in[3];
    const float* mask  = (const float*)d_in[4];
    const float* wq    = (const float*)d_in[5];
    const float* bq    = (const float*)d_in[6];
    const float* wkv   = (const float*)d_in[7];
    const float* bkv   = (const float*)d_in[8];
    const float* wqp   = (const float*)d_in[9];
    const float* bqp   = (const float*)d_in[10];
    const float* wkvp  = (const float*)d_in[11];
    const float* bkvp  = (const float*)d_in[12];
    const float* wb    = (const float*)d_in[13];
    const float* bb    = (const float*)d_in[14];
    const float* hw    = (const float*)d_in[15];
    const float* wout  = (const float*)d_in[16];
    const float* bout  = (const float*)d_in[17];

    const int smem1 = (TJ1*CSd + TJ1*NPROJ) * 4;                    // 128000
    // k_attn3: q 2112 + k 8448 + qp 384 + hw 2 + mi 8 + kp 1600 + logits 8192
    const int smemA = (2112 + 8448 + TI*48 + HG + TI + 64*25 + HG*TI*Nd) * 4; // 82984
    // k_out2: v_s 16384 + z_s 16384 + vp 4608 + a 1024
    const int smemO = (4*TJO*256 + 4*TI*TJO*32 + TJO*288 + TI*Hd*TJO) * 4; // 153600
    const int smem4 = TJ4*FEAT*4;                                   // 77824

    cudaFuncSetAttribute(k_proj,   cudaFuncAttributeMaxDynamicSharedMemorySize, smem1);
    cudaFuncSetAttribute(k_attn3,  cudaFuncAttributeMaxDynamicSharedMemorySize, smemA);
    cudaFuncSetAttribute(k_out2,   cudaFuncAttributeMaxDynamicSharedMemorySize, smemO);
    cudaFuncSetAttribute(k_final2, cudaFuncAttributeMaxDynamicSharedMemorySize, smem4);

    k_trans<<<dim3(FEAT/32, CSd/32), 256>>>(wout);
    k_proj<<<Bd*Nd/TJ1, 256, smem1>>>(s, rot, trans, wq, bq, wkv, bkv,
                                      wqp, bqp, wkvp, bkvp);
    k_bias<<<dim3(Nd, Bd), 256>>>(z, wb, bb);
    k_attn3<<<dim3(Nd/TI, Hd/HG, Bd), 256, smemA>>>(hw, mask);
    k_out2<<<dim3(Nd/TI, Bd), 256, smemO>>>(z, rot, trans);
    k_final2<<<Bd*Nd/TJ4, 256, smem4>>>(bout, (float*)d_out);
}

// round 17
// speedup vs baseline: 1.5889x; 1.0876x over previous
#include <cuda_runtime.h>
#include <math.h>

#define Bd 2
#define Nd 512
#define CSd 256
#define CZd 128
#define Cd 128
#define Hd 8
#define PQKd 8
#define PVd 12
#define HCd (Hd*Cd)          // 1024
#define NPROJ 3744
#define FEAT 2432
#define PPART 2336           // per-token partial: 1024 o + 1024 zp + 288 pt

#define QK_SCALE 0.05103103630798287f   // sqrt(1/384)
#define BIAS_COEF 0.5773502691896258f   // sqrt(1/3)
#define PT_COEF 0.09622504486493763f    // sqrt(1/108)

// ---------------- scratch ----------------------------------------------------
__device__ float g_q[Bd*Nd*HCd];
__device__ float g_k[Bd*Nd*HCd];
__device__ float g_v[Bd*Nd*HCd];
__device__ float g_qpts[Bd*Nd*Hd*PQKd*3];
__device__ float g_kpts[Bd*Nd*Hd*PQKd*3];
__device__ float g_vpts[Bd*Nd*Hd*PVd*3];
__device__ float g_a[Bd*Hd*Nd*Nd];       // softmaxed attention [b][h][i][j]
__device__ float g_bias[Bd*Hd*Nd*Nd];    // BIAS_COEF*(z@wb+bb)  [b][h][i][j]
__device__ float g_part[2*Bd*Nd*PPART];  // j-half partials [jh][tok][2336]
__device__ float g_feats[Bd*Nd*FEAT];
__device__ float g_woutT[FEAT*CSd];      // transposed wout [k][cs]

// ---------------- kernel 1: projections + RoPE + rigid -----------------------
#define TJ1 4
__global__ __launch_bounds__(256, 2)
void k_proj(const float* __restrict__ s,
            const float* __restrict__ rot,
            const float* __restrict__ trans,
            const float* __restrict__ wq,  const float* __restrict__ bq,
            const float* __restrict__ wkv, const float* __restrict__ bkv,
            const float* __restrict__ wqp, const float* __restrict__ bqp,
            const float* __restrict__ wkvp,const float* __restrict__ bkvp)
{
    extern __shared__ float sh[];
    float* s_s = sh;                        // TJ1*256
    float* raw = sh + TJ1*CSd;              // TJ1*NPROJ
    const int tid  = threadIdx.x;
    const int tok0 = blockIdx.x * TJ1;

    for (int idx = tid; idx < TJ1*CSd/4; idx += 256)
        ((float4*)s_s)[idx] = ((const float4*)(s + (size_t)tok0*CSd))[idx];
    __syncthreads();

    for (int oi = tid; oi < NPROJ; oi += 256) {
        const float* wrow; float bias;
        if (oi < 1024)      { wrow = wq   + oi*CSd;        bias = bq[oi]; }
        else if (oi < 3072) { wrow = wkv  + (oi-1024)*CSd; bias = bkv[oi-1024]; }
        else if (oi < 3264) { wrow = wqp  + (oi-3072)*CSd; bias = bqp[oi-3072]; }
        else                { wrow = wkvp + (oi-3264)*CSd; bias = bkvp[oi-3264]; }
        float acc[TJ1];
        #pragma unroll
        for (int t = 0; t < TJ1; t++) acc[t] = 0.0f;
        const float4* w4 = (const float4*)wrow;
        for (int k4 = 0; k4 < CSd/4; k4++) {
            float4 w = w4[k4];
            #pragma unroll
            for (int t = 0; t < TJ1; t++) {
                const float* sp = s_s + t*CSd + k4*4;
                acc[t] = fmaf(w.x, sp[0], acc[t]);
                acc[t] = fmaf(w.y, sp[1], acc[t]);
                acc[t] = fmaf(w.z, sp[2], acc[t]);
                acc[t] = fmaf(w.w, sp[3], acc[t]);
            }
        }
        #pragma unroll
        for (int t = 0; t < TJ1; t++) raw[t*NPROJ + oi] = acc[t] + bias;
    }
    __syncthreads();

    for (int t = 0; t < TJ1; t++) {
        const int tok = tok0 + t;
        const int n   = tok % Nd;
        const float* R = rot + tok*9;
        const float* T = trans + tok*3;
        const float* rw = raw + t*NPROJ;
        for (int job = tid; job < 3296; job += 256) {
            if (job < 2048) {
                const int e = job & 1023;
                const int h = e >> 7, c = e & 127;
                const int d = c & 63;
                float ang = (float)n * expf(-(float)(2*d) * (9.210340371976184f/128.0f));
                float cv, sv; sincosf(ang, &sv, &cv);   // sin first!
                float val, other;
                if (job < 1024) {
                    val   = rw[e];
                    other = (c < 64) ? -rw[e+64] : rw[e-64];
                    g_q[(size_t)tok*HCd + e] = val*cv + other*sv;
                } else {
                    const int base = 1024 + h*256;
                    val   = rw[base + c];
                    other = (c < 64) ? -rw[base + c + 64] : rw[base + c - 64];
                    g_k[(size_t)tok*HCd + h*Cd + c] = val*cv + other*sv;
                }
            } else if (job < 3072) {
                const int e = job - 2048;
                const int h = e >> 7, c = e & 127;
                g_v[(size_t)tok*HCd + e] = rw[1024 + h*256 + 128 + c];
            } else if (job < 3136) {
                const int p = job - 3072;
                float v0 = rw[3072 + p], v1 = rw[3072+64+p], v2 = rw[3072+128+p];
                float x = R[0]*v0 + R[1]*v1 + R[2]*v2 + T[0];
                float y = R[3]*v0 + R[4]*v1 + R[5]*v2 + T[1];
                float zc= R[6]*v0 + R[7]*v1 + R[8]*v2 + T[2];
                float* dst = g_qpts + ((size_t)tok*Hd + (p>>3))*PQKd*3 + (p&7)*3;
                dst[0]=x; dst[1]=y; dst[2]=zc;
            } else {
                const int p = job - 3136;
                float v0 = rw[3264 + p], v1 = rw[3264+160+p], v2 = rw[3264+320+p];
                float x = R[0]*v0 + R[1]*v1 + R[2]*v2 + T[0];
                float y = R[3]*v0 + R[4]*v1 + R[5]*v2 + T[1];
                float zc= R[6]*v0 + R[7]*v1 + R[8]*v2 + T[2];
                const int h = p/20, pp = p%20;
                if (pp < PQKd) {
                    float* dst = g_kpts + ((size_t)tok*Hd + h)*PQKd*3 + pp*3;
                    dst[0]=x; dst[1]=y; dst[2]=zc;
                } else {
                    float* dst = g_vpts + ((size_t)tok*Hd + h)*PVd*3 + (pp-PQKd)*3;
                    dst[0]=x; dst[1]=y; dst[2]=zc;
                }
            }
        }
    }
}

// ---------------- kernel 2: bias = BIAS_COEF*(z@wb^T + bb) -------------------
__global__ void k_bias(const float* __restrict__ z,
                       const float* __restrict__ wb, const float* __restrict__ bb)
{
    __shared__ float4 wb_s[Hd*32];
    __shared__ float4 z_s[32*33];
    __shared__ float  bb_s[Hd];

    const int i = blockIdx.x, b = blockIdx.y;
    const int tid = threadIdx.x;
    const int h = tid >> 5, jj = tid & 31;

    if (tid < Hd*32) wb_s[tid] = ((const float4*)wb)[tid];
    if (tid < Hd) bb_s[tid] = bb[tid];
    __syncthreads();

    const float4* zrow = (const float4*)(z + ((size_t)(b*Nd+i))*Nd*CZd);
    float* brow = g_bias + (((size_t)b*Hd)*Nd + i)*Nd;

    for (int j0 = 0; j0 < Nd; j0 += 32) {
        __syncthreads();
        for (int idx = tid; idx < 32*32; idx += 256) {
            int r = idx >> 5, c4 = idx & 31;
            z_s[r*33 + c4] = zrow[(size_t)(j0+r)*32 + c4];
        }
        __syncthreads();
        float acc = 0.0f;
        #pragma unroll 8
        for (int c4 = 0; c4 < 32; c4++) {
            float4 zv = z_s[jj*33 + c4];
            float4 wv = wb_s[h*32 + c4];
            acc = fmaf(zv.x, wv.x, acc);
            acc = fmaf(zv.y, wv.y, acc);
            acc = fmaf(zv.z, wv.z, acc);
            acc = fmaf(zv.w, wv.w, acc);
        }
        brow[(size_t)h*Nd*Nd + j0 + jj] = BIAS_COEF * (acc + bb_s[h]);
    }
}

// ---------------- kernel 3: logits + softmax (1 head/block, 2 blocks/SM) -----
#define TI 8
__global__ __launch_bounds__(256, 2)
void k_attn4(const float* __restrict__ hwraw, const float* __restrict__ mask)
{
    extern __shared__ float sh[];
    // floats: q_s[1056] | k_s[8448] | qp_s[192] | hw[1] | mi[8] | kp[1600] | logits[4096]
    float4* q_s   = (float4*)sh;                       // [i][33] f4
    float4* k_s   = (float4*)(sh + 1056);              // [64][33] f4
    float*  qp_s  = sh + 1056 + 8448;                  // [i][24]
    float*  hw_s  = qp_s + TI*24;                      // [1]
    float*  mi_s  = hw_s + 1;                          // [8]
    float*  kp_s  = mi_s + TI;                         // [64][25]
    float*  logits= kp_s + 64*25;                      // [i][512]

    const int i0 = blockIdx.x * TI;
    const int h  = blockIdx.y;
    const int b  = blockIdx.z;
    const int tid = threadIdx.x, lane = tid & 31, w = tid >> 5;

    for (int idx4 = tid; idx4 < TI*32; idx4 += 256) {
        int i = idx4 >> 5, c4 = idx4 & 31;
        q_s[i*33 + c4] =
            ((const float4*)g_q)[(size_t)(b*Nd + i0 + i)*256 + h*32 + c4];
    }
    for (int idx = tid; idx < TI*24; idx += 256) {
        int i = idx/24, tt = idx%24;
        qp_s[i*24 + tt] = g_qpts[(size_t)(b*Nd + i0 + i)*192 + h*24 + tt];
    }
    if (tid == 0) hw_s[0] = log1pf(expf(hwraw[h])) * PT_COEF;
    if (tid < TI) mi_s[tid] = mask[b*Nd + i0 + tid];
    __syncthreads();

    const int jloc = tid & 63;
    const int iq   = tid >> 6;
    const float hwh = hw_s[0];

    for (int j0 = 0; j0 < Nd; j0 += 64) {
        __syncthreads();
        for (int idx4 = tid; idx4 < 64*32; idx4 += 256) {
            int r = idx4 >> 5, c4 = idx4 & 31;
            k_s[r*33 + c4] =
                ((const float4*)g_k)[(size_t)(b*Nd + j0 + r)*256 + h*32 + c4];
        }
        for (int idx = tid; idx < 64*24; idx += 256) {
            int r = idx/24, t = idx%24;
            kp_s[r*25 + t] = g_kpts[(size_t)(b*Nd + j0 + r)*192 + h*24 + t];
        }
        __syncthreads();

        const float mj = mask[b*Nd + j0 + jloc];
        #pragma unroll
        for (int half = 0; half < 2; half++) {
            const int ii = iq + half*4;
            const float4* qv = q_s + ii*33;
            const float4* kv = k_s + jloc*33;
            float a0=0.f, a1=0.f, a2=0.f, a3=0.f;
            #pragma unroll
            for (int c4 = 0; c4 < 32; c4 += 4) {
                float4 q0 = qv[c4+0], k0 = kv[c4+0];
                float4 q1 = qv[c4+1], k1 = kv[c4+1];
                float4 q2 = qv[c4+2], k2 = kv[c4+2];
                float4 q3 = qv[c4+3], k3 = kv[c4+3];
                a0 = fmaf(q0.x,k0.x, fmaf(q0.y,k0.y, fmaf(q0.z,k0.z, fmaf(q0.w,k0.w, a0))));
                a1 = fmaf(q1.x,k1.x, fmaf(q1.y,k1.y, fmaf(q1.z,k1.z, fmaf(q1.w,k1.w, a1))));
                a2 = fmaf(q2.x,k2.x, fmaf(q2.y,k2.y, fmaf(q2.z,k2.z, fmaf(q2.w,k2.w, a2))));
                a3 = fmaf(q3.x,k3.x, fmaf(q3.y,k3.y, fmaf(q3.z,k3.z, fmaf(q3.w,k3.w, a3))));
            }
            float qk = (a0 + a1) + (a2 + a3);
            const float* qp = qp_s + ii*24;
            const float* kp = kp_s + jloc*25;
            float d0=0.f, d1=0.f, d2a=0.f;
            #pragma unroll
            for (int t = 0; t < 8; t++) {
                float u0 = qp[t]    - kp[t];
                float u1 = qp[t+8]  - kp[t+8];
                float u2 = qp[t+16] - kp[t+16];
                d0 = fmaf(u0, u0, d0);
                d1 = fmaf(u1, u1, d1);
                d2a= fmaf(u2, u2, d2a);
            }
            float d2 = (d0 + d1) + d2a;
            float bias_v = g_bias[(((size_t)b*Hd + h)*Nd + i0 + ii)*Nd + j0 + jloc];
            float lg = QK_SCALE*qk + bias_v - 0.5f*hwh*d2
                     + (mi_s[ii]*mj - 1.0f)*100000.0f;
            logits[ii*Nd + j0 + jloc] = lg;
        }
    }
    __syncthreads();

    // softmax: warp w -> row i=w
    {
        float* row = logits + w*Nd;
        float m = -1e30f;
        for (int j = lane; j < Nd; j += 32) m = fmaxf(m, row[j]);
        #pragma unroll
        for (int off = 16; off; off >>= 1) m = fmaxf(m, __shfl_xor_sync(0xffffffffu, m, off));
        float sum = 0.0f;
        for (int j = lane; j < Nd; j += 32) {
            float e = expf(row[j] - m);
            row[j] = e;
            sum += e;
        }
        #pragma unroll
        for (int off = 16; off; off >>= 1) sum += __shfl_xor_sync(0xffffffffu, sum, off);
        const float inv = 1.0f/sum;
        float* arow = g_a + (((size_t)b*Hd + h)*Nd + i0 + w)*Nd;
        for (int j = lane; j < Nd; j += 32) arow[j] = row[j]*inv;
    }
}

// ---------------- kernel 4: fused a@{v,z,vpts}, j-split partials -------------
#define TJO 8
__global__ __launch_bounds__(256, 2)
void k_out3(const float* __restrict__ z)
{
    extern __shared__ float sh[];
    float4* v_s   = (float4*)sh;                        // [8j][256] f4 = 8192 f
    float4* z_s   = (float4*)(sh + 4*TJO*256);          // [8i][8j][32] f4 = 8192 f
    float*  vp_s  = sh + 4*TJO*256 + 4*TI*TJO*32;       // [8j][288] = 2304 f
    float*  a_s   = vp_s + TJO*288;                     // [8i][8h][8j] = 512 f

    const int i0 = blockIdx.x * TI;
    const int by = blockIdx.y;                          // (b, jhalf)
    const int b  = by >> 1, jh = by & 1;
    const int tid = threadIdx.x, lane = tid & 31, w = tid >> 5;
    const int iw = i0 + w;

    float4 o_acc[Hd];
    float4 zp_acc[Hd];
    float  pt_acc[9];
    #pragma unroll
    for (int h = 0; h < Hd; h++) {
        o_acc[h]  = make_float4(0.f,0.f,0.f,0.f);
        zp_acc[h] = make_float4(0.f,0.f,0.f,0.f);
    }
    #pragma unroll
    for (int t = 0; t < 9; t++) pt_acc[t] = 0.0f;

    const int jbeg = jh*(Nd/2), jend = jbeg + Nd/2;
    for (int j0 = jbeg; j0 < jend; j0 += TJO) {
        __syncthreads();
        for (int idx4 = tid; idx4 < TJO*256; idx4 += 256) {
            int r = idx4 >> 8, c4 = idx4 & 255;
            v_s[r*256 + c4] = ((const float4*)g_v)[(size_t)(b*Nd + j0 + r)*256 + c4];
        }
        for (int idx4 = tid; idx4 < TI*TJO*32; idx4 += 256) {
            int i = idx4 >> 8, r = (idx4 >> 5) & 7, c4 = idx4 & 31;
            z_s[i*(TJO*32) + r*32 + c4] =
                ((const float4*)z)[((size_t)(b*Nd + i0 + i)*Nd + j0 + r)*32 + c4];
        }
        for (int idx = tid; idx < TJO*288; idx += 256) {
            int r = idx/288, t = idx%288;
            vp_s[r*288 + t] = g_vpts[(size_t)(b*Nd + j0 + r)*288 + t];
        }
        for (int idx = tid; idx < TI*Hd*TJO; idx += 256) {
            int i = idx >> 6, h = (idx >> 3) & 7, jj = idx & 7;
            a_s[(i*Hd + h)*TJO + jj] =
                g_a[(((size_t)b*Hd + h)*Nd + i0 + i)*Nd + j0 + jj];
        }
        __syncthreads();

        for (int jj = 0; jj < TJO; jj++) {
            float av[Hd];
            #pragma unroll
            for (int h = 0; h < Hd; h++) av[h] = a_s[(w*Hd + h)*TJO + jj];
            float4 z4 = z_s[w*(TJO*32) + jj*32 + lane];
            #pragma unroll
            for (int h = 0; h < Hd; h++) {
                float4 v4 = v_s[jj*256 + h*32 + lane];
                o_acc[h].x  = fmaf(av[h], v4.x, o_acc[h].x);
                o_acc[h].y  = fmaf(av[h], v4.y, o_acc[h].y);
                o_acc[h].z  = fmaf(av[h], v4.z, o_acc[h].z);
                o_acc[h].w  = fmaf(av[h], v4.w, o_acc[h].w);
                zp_acc[h].x = fmaf(av[h], z4.x, zp_acc[h].x);
                zp_acc[h].y = fmaf(av[h], z4.y, zp_acc[h].y);
                zp_acc[h].z = fmaf(av[h], z4.z, zp_acc[h].z);
                zp_acc[h].w = fmaf(av[h], z4.w, zp_acc[h].w);
            }
            #pragma unroll
            for (int t = 0; t < 9; t++) {
                int r = lane + 32*t;
                int ht = r/36;
                float aval = a_s[(w*Hd + ht)*TJO + jj];
                pt_acc[t] = fmaf(aval, vp_s[jj*288 + r], pt_acc[t]);
            }
        }
    }

    // write partials for this j-half
    {
        const int tok = b*Nd + iw;
        float* prow = g_part + ((size_t)jh*Bd*Nd + tok)*PPART;
        float4* prow4 = (float4*)prow;
        #pragma unroll
        for (int h = 0; h < Hd; h++) {
            prow4[h*32 + lane]       = o_acc[h];     // o   at [0,1024)
            prow4[256 + h*32 + lane] = zp_acc[h];    // zp  at [1024,2048)
        }
        #pragma unroll
        for (int t = 0; t < 9; t++)
            prow[2048 + lane + 32*t] = pt_acc[t];    // pt  at [2048,2336)
    }
}

// ---------------- kernel 4b: combine halves + inverse rigid + norms ----------
__global__ void k_comb(const float* __restrict__ rot,
                       const float* __restrict__ trans)
{
    __shared__ float pt[288];
    const int tok = blockIdx.x;
    const int tid = threadIdx.x;
    const float* p0 = g_part + (size_t)tok*PPART;
    const float* p1 = g_part + ((size_t)Bd*Nd + tok)*PPART;
    float* frow = g_feats + (size_t)tok*FEAT;

    for (int e = tid; e < 1024; e += 256) {
        frow[e]        = p0[e]      + p1[e];
        frow[1408 + e] = p0[1024+e] + p1[1024+e];
    }
    for (int e = tid; e < 288; e += 256) pt[e] = p0[2048+e] + p1[2048+e];
    __syncthreads();

    if (tid < 96) {
        const int h = tid/PVd, p = tid%PVd;
        const float* src = pt + h*36 + p*3;
        const float* R = rot + tok*9;
        const float* T = trans + tok*3;
        float v0 = src[0]-T[0], v1 = src[1]-T[1], v2 = src[2]-T[2];
        float x = R[0]*v0 + R[3]*v1 + R[6]*v2;
        float y = R[1]*v0 + R[4]*v1 + R[7]*v2;
        float zc= R[2]*v0 + R[5]*v1 + R[8]*v2;
        frow[1024 + tid] = x;
        frow[1120 + tid] = y;
        frow[1216 + tid] = zc;
        frow[1312 + tid] = sqrtf(x*x + y*y + zc*zc + 1e-8f);
    }
}

// ---------------- kernel 5a: transpose wout ----------------------------------
__global__ void k_trans(const float* __restrict__ wout)
{
    __shared__ float tile[32][33];
    const int k0 = blockIdx.x*32, c0 = blockIdx.y*32;
    const int tx = threadIdx.x & 31, ty = threadIdx.x >> 5;
    #pragma unroll
    for (int r = 0; r < 32; r += 8)
        tile[ty+r][tx] = wout[(size_t)(c0+ty+r)*FEAT + k0 + tx];
    __syncthreads();
    #pragma unroll
    for (int r = 0; r < 32; r += 8)
        g_woutT[(size_t)(k0+ty+r)*CSd + c0 + tx] = tile[tx][ty+r];
}

// ---------------- kernel 5b: output projection (coalesced) -------------------
#define TJ4 8
__global__ __launch_bounds__(256, 1)
void k_final2(const float* __restrict__ bout, float* __restrict__ out)
{
    extern __shared__ float f_s[];
    const int tid  = threadIdx.x;
    const int tok0 = blockIdx.x * TJ4;

    for (int idx = tid; idx < TJ4*FEAT/4; idx += 256)
        ((float4*)f_s)[idx] = ((const float4*)(g_feats + (size_t)tok0*FEAT))[idx];
    __syncthreads();

    const int cs = tid;
    float acc[TJ4];
    #pragma unroll
    for (int t = 0; t < TJ4; t++) acc[t] = 0.0f;
    for (int k = 0; k < FEAT; k++) {
        float w = g_woutT[(size_t)k*CSd + cs];
        #pragma unroll
        for (int t = 0; t < TJ4; t++)
            acc[t] = fmaf(w, f_s[t*FEAT + k], acc[t]);
    }
    const float bv = bout[cs];
    #pragma unroll
    for (int t = 0; t < TJ4; t++) out[(size_t)(tok0+t)*CSd + cs] = acc[t] + bv;
}

// ---------------- launch ------------------------------------------------------
extern "C" void kernel_launch(void* const* d_in, const int* in_sizes, int n_in,
                              void* d_out, int out_size)
{
    const float* s     = (const float*)d_in[0];
    const float* z     = (const float*)d_in[1];
    const float* rot   = (const float*)d_in[2];
    const float* trans = (const float*)d_in[3];
    const float* mask  = (const float*)d_in[4];
    const float* wq    = (const float*)d_in[5];
    const float* bq    = (const float*)d_in[6];
    const float* wkv   = (const float*)d_in[7];
    const float* bkv   = (const float*)d_in[8];
    const float* wqp   = (const float*)d_in[9];
    const float* bqp   = (const float*)d_in[10];
    const float* wkvp  = (const float*)d_in[11];
    const float* bkvp  = (const float*)d_in[12];
    const float* wb    = (const float*)d_in[13];
    const float* bb    = (const float*)d_in[14];
    const float* hw    = (const float*)d_in[15];
    const float* wout  = (const float*)d_in[16];
    const float* bout  = (const float*)d_in[17];

    const int smem1 = (TJ1*CSd + TJ1*NPROJ) * 4;                    // 64000
    // k_attn4: q 1056 + k 8448 + qp 192 + hw 1 + mi 8 + kp 1600 + logits 4096
    const int smemA = (1056 + 8448 + TI*24 + 1 + TI + 64*25 + TI*Nd) * 4;  // 61604
    // k_out3: v 8192 + z 8192 + vp 2304 + a 512
    const int smemO = (4*TJO*256 + 4*TI*TJO*32 + TJO*288 + TI*Hd*TJO) * 4; // 76800
    const int smem4 = TJ4*FEAT*4;                                   // 77824

    cudaFuncSetAttribute(k_proj,   cudaFuncAttributeMaxDynamicSharedMemorySize, smem1);
    cudaFuncSetAttribute(k_attn4,  cudaFuncAttributeMaxDynamicSharedMemorySize, smemA);
    cudaFuncSetAttribute(k_out3,   cudaFuncAttributeMaxDynamicSharedMemorySize, smemO);
    cudaFuncSetAttribute(k_final2, cudaFuncAttributeMaxDynamicSharedMemorySize, smem4);

    k_trans<<<dim3(FEAT/32, CSd/32), 256>>>(wout);
    k_proj<<<Bd*Nd/TJ1, 256, smem1>>>(s, rot, trans, wq, bq, wkv, bkv,
                                      wqp, bqp, wkvp, bkvp);
    k_bias<<<dim3(Nd, Bd), 256>>>(z, wb, bb);
    k_attn4<<<dim3(Nd/TI, Hd, Bd), 256, smemA>>>(hw, mask);
    k_out3<<<dim3(Nd/TI, Bd*2), 256, smemO>>>(z);
    k_comb<<<Bd*Nd, 256>>>(rot, trans);
    k_final2<<<Bd*Nd/TJ4, 256, smem4>>>(bout, (float*)d_out);
}